// round 15
// baseline (speedup 1.0000x reference)
#include <cuda_runtime.h>
#include <cuda_fp16.h>
#include <stdint.h>

// Problem constants
#define S_FULL   4096
#define HIDDIM   1024
#define NHEADS   16
#define HEADDIM  64
#define SEQ_E    2048
#define NBATCH   2
#define MROWS    4096              // compact even rows (both batches)
#define NKB      16                // k-blocks of 64
#define WSTRIDE  ((size_t)HIDDIM * HIDDIM)
// 0.125 * log2(e): folded into Wq so S emerges in log2 domain
#define QK_LOG2SCALE 0.1803368801111244f

// Scratch (__device__ globals; no runtime allocation allowed)
__device__ __half g_hs[(size_t)MROWS * HIDDIM];            // hidden states fp16
__device__ __half g_act[(size_t)MROWS * HIDDIM];           // attn out fp16
__device__ __half g_wh[4][(size_t)HIDDIM * HIDDIM];        // weights fp16
__device__ __half g_qs[(size_t)MROWS * NHEADS * 64];       // Q fp16 (pre-scaled)
__device__ __half g_ks[(size_t)MROWS * NHEADS * 64];       // K fp16
__device__ __half g_vs[(size_t)MROWS * NHEADS * 64];       // V fp16

// ---------------------------------------------------------------------------
// PTX helpers (non-arch-specific; compile at plain sm_103)
// ---------------------------------------------------------------------------
__device__ __forceinline__ uint32_t smem_u32(const void* p) {
    uint32_t a;
    asm("{ .reg .u64 t; cvta.to.shared.u64 t, %1; cvt.u32.u64 %0, t; }"
        : "=r"(a) : "l"(p));
    return a;
}

__device__ __forceinline__ void cp_async16(uint32_t dst, const void* src) {
    asm volatile("cp.async.cg.shared.global [%0], [%1], 16;"
                 :: "r"(dst), "l"(src) : "memory");
}

__device__ __forceinline__ void ldm_x4(uint32_t& r0, uint32_t& r1,
                                       uint32_t& r2, uint32_t& r3,
                                       uint32_t addr) {
    asm volatile("ldmatrix.sync.aligned.m8n8.x4.shared.b16 {%0,%1,%2,%3}, [%4];"
                 : "=r"(r0), "=r"(r1), "=r"(r2), "=r"(r3) : "r"(addr));
}

__device__ __forceinline__ void ldm_x4_trans(uint32_t& r0, uint32_t& r1,
                                             uint32_t& r2, uint32_t& r3,
                                             uint32_t addr) {
    asm volatile("ldmatrix.sync.aligned.m8n8.x4.trans.shared.b16 {%0,%1,%2,%3}, [%4];"
                 : "=r"(r0), "=r"(r1), "=r"(r2), "=r"(r3) : "r"(addr));
}

__device__ __forceinline__ void mma_16816(float* d, const uint32_t* a,
                                          const uint32_t* b) {
    asm volatile(
        "mma.sync.aligned.m16n8k16.row.col.f32.f16.f16.f32 "
        "{%0,%1,%2,%3}, {%4,%5,%6,%7}, {%8,%9}, {%0,%1,%2,%3};"
        : "+f"(d[0]), "+f"(d[1]), "+f"(d[2]), "+f"(d[3])
        : "r"(a[0]), "r"(a[1]), "r"(a[2]), "r"(a[3]), "r"(b[0]), "r"(b[1]));
}

__device__ __forceinline__ uint32_t pack2(float x, float y) {
    __half2 h = __floats2half2_rn(x, y);
    return *reinterpret_cast<uint32_t*>(&h);
}

// 2-wide fp16 exp2 (single MUFU op); exp2(-inf) = 0 handles the causal mask
__device__ __forceinline__ uint32_t h2exp2_u32(uint32_t x) {
    uint32_t r;
    asm("ex2.approx.f16x2 %0, %1;" : "=r"(r) : "r"(x));
    return r;
}

// ---------------------------------------------------------------------------
// Fused elementwise prep: one launch, 4 independent float4 per thread (MLP=4).
//   blocks [0,1024):    hidden-state gather -> fp16 g_hs
//   blocks [1024,2048): 4 weight matrices fp32 -> fp16 (Wq pre-scaled)
//   blocks [2048,3072): odd output rows = bo broadcast
// ---------------------------------------------------------------------------
__global__ __launch_bounds__(256) void prep(const float* __restrict__ hs,
                                            const float* __restrict__ W0,
                                            const float* __restrict__ W1,
                                            const float* __restrict__ W2,
                                            const float* __restrict__ W3,
                                            const float* __restrict__ bo,
                                            float* __restrict__ out,
                                            __half* __restrict__ act,
                                            __half* __restrict__ wh)
{
    const int blk = blockIdx.x;
    const int tid = threadIdx.x;
    const int c4  = tid << 2;

    if (blk < 1024) {
        float4 a[4];
#pragma unroll
        for (int r = 0; r < 4; r++) {
            int m = blk * 4 + r;
            int srow = ((m >> 11) << 12) + ((m & 2047) << 1);
            a[r] = *(const float4*)(hs + (size_t)srow * HIDDIM + c4);
        }
#pragma unroll
        for (int r = 0; r < 4; r++) {
            __half* p = act + (size_t)(blk * 4 + r) * HIDDIM + c4;
            *(__half2*)(p)     = __floats2half2_rn(a[r].x, a[r].y);
            *(__half2*)(p + 2) = __floats2half2_rn(a[r].z, a[r].w);
        }
    } else if (blk < 2048) {
        int sub  = blk - 1024;
        int wsel = sub >> 8;
        int mb   = (sub & 255) * 4;
        const float* W = (wsel == 0) ? W0 : (wsel == 1) ? W1 : (wsel == 2) ? W2 : W3;
        float sc = (wsel == 0) ? QK_LOG2SCALE : 1.0f;
        float4 a[4];
#pragma unroll
        for (int r = 0; r < 4; r++)
            a[r] = *(const float4*)(W + (size_t)(mb + r) * HIDDIM + c4);
#pragma unroll
        for (int r = 0; r < 4; r++) {
            __half* p = wh + (size_t)wsel * WSTRIDE + (size_t)(mb + r) * HIDDIM + c4;
            *(__half2*)(p)     = __floats2half2_rn(a[r].x * sc, a[r].y * sc);
            *(__half2*)(p + 2) = __floats2half2_rn(a[r].z * sc, a[r].w * sc);
        }
    } else {
        int sub = blk - 2048;
        float4 bv = *(const float4*)(bo + c4);
#pragma unroll
        for (int r = 0; r < 4; r++) {
            int row = sub * 4 + r;               // 0..4095 odd-row index
            *(float4*)(out + (size_t)((row << 1) + 1) * HIDDIM + c4) = bv;
        }
    }
}

// ---------------------------------------------------------------------------
// HMMA NT GEMM core (plain fp16, fp32 accum): CTA 128x128, 8 warps 2x4,
// K=1024, k-block 64, THREE-stage cp.async pipeline, ONE sync per k-iter.
// ---------------------------------------------------------------------------
#define GEMM_SMEM 98304    // 3 stages x (16KB A + 16KB B)

template <typename EPI>
__device__ __forceinline__ void gemm_body(const __half* __restrict__ A,
                                          const __half* __restrict__ B,
                                          EPI epi)
{
    extern __shared__ char smem[];
    const uint32_t sb = smem_u32(smem);
    const int tid  = threadIdx.x;
    const int lane = tid & 31;
    const int w    = tid >> 5;
    const int wm   = w >> 2;
    const int wn   = w & 3;
    const int m0   = blockIdx.y << 7;
    const int n0   = blockIdx.x << 7;

    const __half* Ab = A + (size_t)m0 * HIDDIM;
    const __half* Bb = B + (size_t)n0 * HIDDIM;

    auto load_chunk = [&](int c, int s) {
        uint32_t sA = sb + s * 32768;
        uint32_t sB = sb + s * 32768 + 16384;
#pragma unroll
        for (int r = 0; r < 4; r++) {
            int g = tid + (r << 8);
            int row = g >> 3, c16 = g & 7;
            uint32_t cc = c16 ^ (row & 7);
            cp_async16(sA + row * 128 + (cc << 4),
                       Ab + (size_t)row * HIDDIM + c * 64 + c16 * 8);
        }
#pragma unroll
        for (int r = 0; r < 4; r++) {
            int g = tid + (r << 8);
            int row = g >> 3, c16 = g & 7;
            uint32_t cc = c16 ^ (row & 7);
            cp_async16(sB + row * 128 + (cc << 4),
                       Bb + (size_t)row * HIDDIM + c * 64 + c16 * 8);
        }
    };

    float acc[4][4][4] = {};

    load_chunk(0, 0);
    asm volatile("cp.async.commit_group;" ::: "memory");
    load_chunk(1, 1);
    asm volatile("cp.async.commit_group;" ::: "memory");

    const int a_row = wm * 64 + (lane & 15);
    const int a_kc  = lane >> 4;
    const int b_row = wn * 32 + (lane & 7) + ((lane >> 4) << 3);
    const int b_kc  = (lane >> 3) & 1;

    int buf = 0;
    for (int c = 0; c < NKB; c++) {
        if (c < NKB - 1) asm volatile("cp.async.wait_group 1;" ::: "memory");
        else             asm volatile("cp.async.wait_group 0;" ::: "memory");
        __syncthreads();

        // Prefetch chunk c+2 into the stage freed at the barrier above.
        if (c + 2 < NKB) {
            int nbuf = buf + 2;
            if (nbuf >= 3) nbuf -= 3;
            load_chunk(c + 2, nbuf);
            asm volatile("cp.async.commit_group;" ::: "memory");
        }

        const uint32_t sA = sb + buf * 32768;
        const uint32_t sB = sb + buf * 32768 + 16384;
#pragma unroll
        for (int kf = 0; kf < 4; kf++) {
            uint32_t ah[4][4], b[2][4];
#pragma unroll
            for (int nf2 = 0; nf2 < 2; nf2++) {
                int row = b_row + nf2 * 16;
                uint32_t cc = (2 * kf + b_kc) ^ (row & 7);
                ldm_x4(b[nf2][0], b[nf2][1], b[nf2][2], b[nf2][3],
                       sB + row * 128 + (cc << 4));
            }
#pragma unroll
            for (int mf = 0; mf < 4; mf++) {
                int row = a_row + mf * 16;
                uint32_t cc = (2 * kf + a_kc) ^ (row & 7);
                ldm_x4(ah[mf][0], ah[mf][1], ah[mf][2], ah[mf][3],
                       sA + row * 128 + (cc << 4));
            }
#pragma unroll
            for (int mf = 0; mf < 4; mf++)
#pragma unroll
                for (int nf = 0; nf < 4; nf++) {
                    uint32_t bb[2] = { b[nf >> 1][(nf & 1) * 2],
                                       b[nf >> 1][(nf & 1) * 2 + 1] };
                    mma_16816(acc[mf][nf], ah[mf], bb);
                }
        }
        if (++buf == 3) buf = 0;
    }

#pragma unroll
    for (int mf = 0; mf < 4; mf++) {
#pragma unroll
        for (int nf = 0; nf < 4; nf++) {
            int col = n0 + wn * 32 + nf * 8 + (lane & 3) * 2;
#pragma unroll
            for (int rg = 0; rg < 2; rg++) {
                int m = m0 + wm * 64 + mf * 16 + rg * 8 + (lane >> 2);
                epi(m, col, acc[mf][nf][rg * 2], acc[mf][nf][rg * 2 + 1]);
            }
        }
    }
}

// Fused QKV GEMM: blockIdx.z selects weight + destination
__global__ __launch_bounds__(256, 2) void gemm_qkv(const __half* __restrict__ A,
                                                   const __half* __restrict__ Bw,
                                                   __half* __restrict__ O0,
                                                   __half* __restrict__ O1,
                                                   __half* __restrict__ O2)
{
    const int z = blockIdx.z;
    const __half* B = Bw + (size_t)z * WSTRIDE;
    __half* Cb = (z == 0) ? O0 : (z == 1) ? O1 : O2;
    gemm_body(A, B, [&](int m, int col, float vx, float vy) {
        int head = col >> 6, d = col & 63;
        __half* p = Cb + (size_t)m * (NHEADS * 64) + head * 64 + d;
        *(uint32_t*)p = pack2(vx, vy);
    });
}

// Final projection: fp32 scatter to even output rows + bias
__global__ __launch_bounds__(256, 2) void gemm_out(const __half* __restrict__ A,
                                                   const __half* __restrict__ B,
                                                   const float* __restrict__ bias,
                                                   float* __restrict__ C)
{
    gemm_body(A, B, [&](int m, int col, float vx, float vy) {
        int crow = ((m >> 11) << 12) + ((m & 2047) << 1);
        float2 v = make_float2(vx + bias[col], vy + bias[col + 1]);
        *(float2*)(C + (size_t)crow * HIDDIM + col) = v;
    });
}

// ---------------------------------------------------------------------------
// HMMA flash attention, fp16, causal, no max-tracking (scores bounded).
// Q pre-scaled by 0.125*log2e -> S in log2 domain; P = ex2.approx.f16x2(S).
// Row sums l via ones-column MMA on the same fp16 P.
// R15: in the diagonal tile, warp w skips 16-row k-groups g16 > w entirely
// (their contribution is exactly +0) — bit-identical, ~7/16 less diag work.
// CTA = 128 q-rows x one (b,h); 8 warps, warp-local rows. Smem 80KB.
// ---------------------------------------------------------------------------
#define SQ_OFF   0
#define SK_OFF   16384
#define SV_OFF   49152
#define ATT_SMEM 81920

__global__ __launch_bounds__(256, 2) void attn_mma()
{
    extern __shared__ char smem[];
    const uint32_t sb = smem_u32(smem);
    const int tid  = threadIdx.x;
    const int lane = tid & 31;
    const int w    = tid >> 5;
    const int bh = blockIdx.y;
    const int b = bh >> 4, h = bh & 15;
    const int qt  = (int)gridDim.x - 1 - (int)blockIdx.x;  // longest first
    const int q0  = qt << 7;
    const int nkt = qt + 1;

    const __half* qsrc = g_qs + (size_t)(b * SEQ_E + q0) * (NHEADS * 64) + h * 64;
    const __half* kbas = g_ks + (size_t)(b * SEQ_E) * (NHEADS * 64) + h * 64;
    const __half* vbas = g_vs + (size_t)(b * SEQ_E) * (NHEADS * 64) + h * 64;

    // Q tile: 128 rows x 128B (8 chunks/row)
#pragma unroll
    for (int r = 0; r < 4; r++) {
        int g = tid + (r << 8);
        int row = g >> 3, c = g & 7;
        uint32_t cc = c ^ (row & 7);
        cp_async16(sb + SQ_OFF + row * 128 + (cc << 4),
                   qsrc + (size_t)row * (NHEADS * 64) + c * 8);
    }
    asm volatile("cp.async.commit_group;" ::: "memory");

    auto loadKV = [&](int kt, int s) {
        const __half* kp = kbas + (size_t)(kt << 7) * (NHEADS * 64);
        const __half* vp = vbas + (size_t)(kt << 7) * (NHEADS * 64);
        uint32_t dK = sb + SK_OFF + s * 16384;
        uint32_t dV = sb + SV_OFF + s * 16384;
#pragma unroll
        for (int r = 0; r < 4; r++) {
            int g = tid + (r << 8);
            int row = g >> 3, c = g & 7;
            uint32_t cc = c ^ (row & 7);
            cp_async16(dK + row * 128 + (cc << 4),
                       kp + (size_t)row * (NHEADS * 64) + c * 8);
        }
#pragma unroll
        for (int r = 0; r < 4; r++) {
            int g = tid + (r << 8);
            int row = g >> 3, c = g & 7;
            uint32_t cc = c ^ (row & 7);
            cp_async16(dV + row * 128 + (cc << 4),
                       vp + (size_t)row * (NHEADS * 64) + c * 8);
        }
        asm volatile("cp.async.commit_group;" ::: "memory");
    };

    loadKV(0, 0);
    if (nkt > 1) {
        loadKV(1, 1);
        asm volatile("cp.async.wait_group 1;" ::: "memory");
    } else {
        asm volatile("cp.async.wait_group 0;" ::: "memory");
    }
    __syncthreads();

    // Q fragments: 4 k16-steps over d=64
    uint32_t qf[4][4];
    {
        int arow = (w << 4) + (lane & 15);
        int cb   = lane >> 4;
#pragma unroll
        for (int ks = 0; ks < 4; ks++) {
            int c = 2 * ks + cb;
            uint32_t cc = (c ^ arow) & 7;
            ldm_x4(qf[ks][0], qf[ks][1], qf[ks][2], qf[ks][3],
                   sb + SQ_OFF + arow * 128 + (cc << 4));
        }
    }

    float oacc[8][4] = {};
    float lacc[4] = {};                    // ones-column MMA row sums
    const uint32_t ONE2 = 0x3C003C00u;     // fp16 {1.0, 1.0}
    const uint32_t bones[2] = { ONE2, ONE2 };
    const int qg0 = q0 + (w << 4) + (lane >> 2);
    const int qg1 = qg0 + 8;

    const int brl = (lane & 7) + ((lane >> 4) << 3);
    const int bkb = (lane >> 3) & 1;
    const int gi     = lane >> 3;
    const int krow_b = ((gi & 1) << 3) + (lane & 7);
    const int cbit   = gi >> 1;

    for (int kt = 0; kt < nkt; kt++) {
        const int s = kt & 1;
        const uint32_t sK = sb + SK_OFF + s * 16384;
        const uint32_t sV = sb + SV_OFF + s * 16384;
        const int k0g = kt << 7;
        const bool diag = (kt == nkt - 1);

#pragma unroll
        for (int half = 0; half < 2; half++) {
            // ---- S = Q K^T for this 64-col half (log2 domain) ----
            float sacc[8][4];
#pragma unroll
            for (int i = 0; i < 8; i++)
#pragma unroll
                for (int e = 0; e < 4; e++) sacc[i][e] = 0.f;

#pragma unroll
            for (int nt2 = 0; nt2 < 4; nt2++) {
                int g16 = (half << 2) + nt2;
                if (diag && g16 > w) continue;      // fully-masked: exact +0
#pragma unroll
                for (int kf = 0; kf < 4; kf++) {
                    int row = (g16 << 4) + brl;
                    uint32_t cc = ((2 * kf + bkb) ^ row) & 7;
                    uint32_t bf[4];
                    ldm_x4(bf[0], bf[1], bf[2], bf[3], sK + row * 128 + (cc << 4));
                    uint32_t bb0[2] = { bf[0], bf[1] };
                    uint32_t bb1[2] = { bf[2], bf[3] };
                    mma_16816(sacc[2 * nt2],     qf[kf], bb0);
                    mma_16816(sacc[2 * nt2 + 1], qf[kf], bb1);
                }
            }

            // ---- fused mask + exp2 + PV per 16-row k-group ----
#pragma unroll
            for (int ksl = 0; ksl < 4; ksl++) {
                int g16 = (half << 2) + ksl;
                if (diag && g16 > w) continue;      // fully-masked: exact +0
                float s0 = sacc[2 * ksl][0],     s1 = sacc[2 * ksl][1];
                float s2 = sacc[2 * ksl][2],     s3 = sacc[2 * ksl][3];
                float u0 = sacc[2 * ksl + 1][0], u1 = sacc[2 * ksl + 1][1];
                float u2 = sacc[2 * ksl + 1][2], u3 = sacc[2 * ksl + 1][3];
                if (diag) {
                    int kgA = k0g + (g16 << 4) + ((lane & 3) << 1);
                    int kgB = kgA + 8;
                    if (kgA     > qg0) s0 = -1e30f;
                    if (kgA + 1 > qg0) s1 = -1e30f;
                    if (kgA     > qg1) s2 = -1e30f;
                    if (kgA + 1 > qg1) s3 = -1e30f;
                    if (kgB     > qg0) u0 = -1e30f;
                    if (kgB + 1 > qg0) u1 = -1e30f;
                    if (kgB     > qg1) u2 = -1e30f;
                    if (kgB + 1 > qg1) u3 = -1e30f;
                }
                uint32_t ah[4];
                ah[0] = h2exp2_u32(pack2(s0, s1));
                ah[1] = h2exp2_u32(pack2(s2, s3));
                ah[2] = h2exp2_u32(pack2(u0, u1));
                ah[3] = h2exp2_u32(pack2(u2, u3));

                mma_16816(lacc, ah, bones);
                int krow = (g16 << 4) + krow_b;
#pragma unroll
                for (int g = 0; g < 4; g++) {
                    int ch = 2 * g + cbit;
                    uint32_t cc = (ch ^ krow) & 7;
                    uint32_t vh[4];
                    ldm_x4_trans(vh[0], vh[1], vh[2], vh[3],
                                 sV + krow * 128 + (cc << 4));
                    uint32_t b0[2] = { vh[0], vh[1] }, b1[2] = { vh[2], vh[3] };
                    mma_16816(oacc[2 * g],     ah, b0);
                    mma_16816(oacc[2 * g + 1], ah, b1);
                }
            }
        }

        __syncthreads();                       // all warps done reading buf s
        if (kt + 2 < nkt) loadKV(kt + 2, s);
        if (kt + 1 < nkt) {
            if (kt + 2 < nkt) asm volatile("cp.async.wait_group 1;" ::: "memory");
            else              asm volatile("cp.async.wait_group 0;" ::: "memory");
            __syncthreads();
        }
    }

    // ---- normalize by MMA row sums; write plain fp16 into g_act ----
    float inv0 = 1.0f / lacc[0], inv1 = 1.0f / lacc[2];
    const size_t row0 = (size_t)(b * SEQ_E + q0 + (w << 4) + (lane >> 2));
    const int dbase = (lane & 3) << 1;
#pragma unroll
    for (int j = 0; j < 8; j++) {
        int d = dbase + (j << 3);
        __half* p0 = g_act + row0 * HIDDIM + h * 64 + d;
        *(uint32_t*)p0 = pack2(oacc[j][0] * inv0, oacc[j][1] * inv0);
        __half* p1 = g_act + (row0 + 8) * HIDDIM + h * 64 + d;
        *(uint32_t*)p1 = pack2(oacc[j][2] * inv1, oacc[j][3] * inv1);
    }
}

// ---------------------------------------------------------------------------
extern "C" void kernel_launch(void* const* d_in, const int* in_sizes, int n_in,
                              void* d_out, int out_size)
{
    const float* hs = (const float*)d_in[0];
    const float* Wq = (const float*)d_in[1];
    const float* Wk = (const float*)d_in[2];
    const float* Wv = (const float*)d_in[3];
    const float* Wo = (const float*)d_in[4];
    const float* bo = (const float*)d_in[5];
    float* out = (float*)d_out;

    __half *ghs, *gac, *gwh, *gqs, *gks, *gvs;
    cudaGetSymbolAddress((void**)&ghs, g_hs);
    cudaGetSymbolAddress((void**)&gac, g_act);
    cudaGetSymbolAddress((void**)&gwh, g_wh);
    cudaGetSymbolAddress((void**)&gqs, g_qs);
    cudaGetSymbolAddress((void**)&gks, g_ks);
    cudaGetSymbolAddress((void**)&gvs, g_vs);

    cudaFuncSetAttribute(gemm_qkv, cudaFuncAttributeMaxDynamicSharedMemorySize, GEMM_SMEM);
    cudaFuncSetAttribute(gemm_out, cudaFuncAttributeMaxDynamicSharedMemorySize, GEMM_SMEM);
    cudaFuncSetAttribute(attn_mma, cudaFuncAttributeMaxDynamicSharedMemorySize, ATT_SMEM);

    // One fused elementwise pass: hs gather, 4x weight convert, odd-row fill
    prep<<<3072, 256>>>(hs, Wq, Wk, Wv, Wo, bo, out, ghs, gwh);

    gemm_qkv<<<dim3(HIDDIM / 128, MROWS / 128, 3), 256, GEMM_SMEM>>>(
        ghs, gwh, gqs, gks, gvs);

    // attn reads g_qs/g_ks/g_vs and writes fp16 output into g_act
    attn_mma<<<dim3(SEQ_E / 128, NBATCH * NHEADS), 256, ATT_SMEM>>>();

    gemm_out<<<dim3(HIDDIM / 128, MROWS / 128), 256, GEMM_SMEM>>>(
        gac, gwh + 3 * WSTRIDE, bo, out);
}